// round 13
// baseline (speedup 1.0000x reference)
#include <cuda_runtime.h>
#include <cuda_bf16.h>
#include <cstdint>

#define DEVINL __device__ __forceinline__

// Shapes: score [2,16,2048,2048] f32, value [2,16,2048,128] f32 -> out [2,16,2048,128] f32
static constexpr int S_ = 2048;
static constexpr int D_ = 128;
static constexpr int BH = 32;
static constexpr int KB = 64;             // K per chunk
static constexpr int CHUNKS = S_ / KB;    // 32
static constexpr int MT = 64;             // CTA M tile
static constexpr int STAGES = 4;

// Padded smem rows: 64 bf16 + 8 pad = 144 bytes (ldmatrix conflict-free)
static constexpr int ROWB = 144;
static constexpr int A_BYTES = MT * ROWB;               // 9216
static constexpr int B_BYTES = 128 * ROWB;              // 18432
static constexpr int STAGE_BYTES = A_BYTES + B_BYTES;   // 27648
static constexpr int SMEM_TOTAL = STAGES * STAGE_BYTES; // 110592 -> 2 CTAs/SM

// Prequantized+transposed value: vt[bh][d][k] bf16, K contiguous (16 MB scratch)
__device__ __align__(16) __nv_bfloat16 g_vt[(size_t)BH * D_ * S_];

DEVINL uint32_t smem_u32(const void* p) {
    uint32_t a;
    asm("{ .reg .u64 t; cvta.to.shared.u64 t, %1; cvt.u32.u64 %0, t; }" : "=r"(a) : "l"(p));
    return a;
}

// Quantize: round-half-even(x/scale) clamped to [-129, 127] (faithful to reference)
DEVINL float quant1(float x, float inv) {
    return fminf(fmaxf(rintf(x * inv), -129.0f), 127.0f);
}
DEVINL uint32_t packq2(float a, float b, float inv) {
    __nv_bfloat162 h = __floats2bfloat162_rn(quant1(a, inv), quant1(b, inv));
    return *reinterpret_cast<uint32_t*>(&h);
}

DEVINL void cp_async16(uint32_t saddr, const void* gaddr) {
    asm volatile("cp.async.cg.shared.global [%0], [%1], 16;" :: "r"(saddr), "l"(gaddr));
}
DEVINL void cp_commit() { asm volatile("cp.async.commit_group;"); }
template <int N> DEVINL void cp_wait() {
    asm volatile("cp.async.wait_group %0;" :: "n"(N) : "memory");
}

DEVINL void ldm4(uint32_t& r0, uint32_t& r1, uint32_t& r2, uint32_t& r3, uint32_t addr) {
    asm volatile("ldmatrix.sync.aligned.m8n8.x4.shared.b16 {%0,%1,%2,%3}, [%4];"
                 : "=r"(r0), "=r"(r1), "=r"(r2), "=r"(r3) : "r"(addr));
}

DEVINL void mma16816(float* c, const uint32_t* a, uint32_t b0, uint32_t b1) {
    asm volatile(
        "mma.sync.aligned.m16n8k16.row.col.f32.bf16.bf16.f32 "
        "{%0,%1,%2,%3}, {%4,%5,%6,%7}, {%8,%9}, {%0,%1,%2,%3};"
        : "+f"(c[0]), "+f"(c[1]), "+f"(c[2]), "+f"(c[3])
        : "r"(a[0]), "r"(a[1]), "r"(a[2]), "r"(a[3]), "r"(b0), "r"(b1));
}

// ---------------------------------------------------------------------------
// Kernel 1: quantize + transpose value -> g_vt[bh][d][k]
// ---------------------------------------------------------------------------
__global__ void quant_transpose_v(const float* __restrict__ value,
                                  const float* __restrict__ ksc) {
    __shared__ __nv_bfloat16 tile[32][34];
    const float inv = 1.0f / ksc[0];
    const int bh = blockIdx.z;
    const int kt = blockIdx.x;
    const int dt = blockIdx.y;
    const int tx = threadIdx.x;
    const int ty = threadIdx.y;

    const float* vp = value + ((size_t)bh * S_ + (size_t)kt * 32) * D_ + dt * 32;
    #pragma unroll
    for (int j = 0; j < 4; j++) {
        int k = ty + 8 * j;
        tile[k][tx] = __float2bfloat16(quant1(vp[(size_t)k * D_ + tx], inv));
    }
    __syncthreads();
    __nv_bfloat16* op = g_vt + ((size_t)bh * D_ + (size_t)dt * 32) * S_ + kt * 32;
    #pragma unroll
    for (int j = 0; j < 4; j++) {
        int d = ty + 8 * j;
        op[(size_t)d * S_ + tx] = tile[tx][d];
    }
}

// ---------------------------------------------------------------------------
// Kernel 2: fused quantize(score) + bf16 mma.sync GEMM, 4-stage ring,
// 2-iteration load runway. 256 threads, tile M64 x N128, warp tile 32x32.
// Body kt: LDG A(kt+2) raw -> cp.async B(kt+2) -> quant+STS A(kt+1)
//          -> wait_group 2 -> barrier -> MMA(kt).
// ---------------------------------------------------------------------------
__global__ void __launch_bounds__(256, 2)
sqbmm_gemm(const float* __restrict__ score,
           const float* __restrict__ qsc,
           const float* __restrict__ ksc,
           float* __restrict__ out) {
    extern __shared__ char smem[];
    const uint32_t sb = smem_u32(smem);
    const int tid  = threadIdx.x;
    const int lane = tid & 31;
    const int w    = tid >> 5;
    const int bx   = blockIdx.x;
    const int bh   = bx >> 5;        // 32 M-tiles per (b,h)
    const int mblk = bx & 31;

    const float inv_q = 1.0f / qsc[0];
    const float* arow = score + ((size_t)bh * S_ + (size_t)mblk * MT) * S_;
    const __nv_bfloat16* bbase = g_vt + (size_t)bh * D_ * S_;

    auto stage = [&](int c) { return sb + (uint32_t)((c & 3) * STAGE_BYTES); };

    // A chunk: 64 rows x 64 cols fp32 = 1024 float4, 4/thread. Banks alternate.
    float4 raw[2][4];

    auto ldgA = [&](int c) {
        float4* r = raw[c & 1];
        const int kk = c * KB;
        #pragma unroll
        for (int i = 0; i < 4; i++) {
            int idx = tid + i * 256;
            int row = idx >> 4;       // 0..63
            int c4  = idx & 15;       // 0..15
            r[i] = *reinterpret_cast<const float4*>(arow + (size_t)row * S_ + kk + c4 * 4);
        }
    };
    auto stsA = [&](int c) {
        const float4* r = raw[c & 1];
        const uint32_t dst = stage(c);
        #pragma unroll
        for (int i = 0; i < 4; i++) {
            int idx = tid + i * 256;
            int row = idx >> 4;
            int c4  = idx & 15;
            uint32_t u0 = packq2(r[i].x, r[i].y, inv_q);
            uint32_t u1 = packq2(r[i].z, r[i].w, inv_q);
            asm volatile("st.shared.v2.b32 [%0], {%1,%2};"
                         :: "r"(dst + (uint32_t)(row * ROWB + c4 * 8)),
                            "r"(u0), "r"(u1) : "memory");
        }
    };
    // B chunk: 128 rows x 128B = 1024 x 16B, 4/thread, one commit.
    auto cpB = [&](int c) {
        const uint32_t dst = stage(c) + A_BYTES;
        const int kk = c * KB;
        #pragma unroll
        for (int i = 0; i < 4; i++) {
            int idx = tid + i * 256;
            int d  = idx >> 3;        // 0..127
            int cc = idx & 7;         // 0..7
            cp_async16(dst + (uint32_t)(d * ROWB + cc * 16),
                       bbase + (size_t)d * S_ + kk + cc * 8);
        }
        cp_commit();
    };

    // warp tile 32(m) x 32(n); warp grid 2x4
    const int wm = (w >> 2) * 32;
    const int wn = (w & 3) * 32;
    const uint32_t a_lm = (uint32_t)((wm + (lane & 15)) * ROWB + (lane >> 4) * 16);
    const uint32_t b_lm = (uint32_t)((wn + (lane & 7) + ((lane & 16) ? 8 : 0)) * ROWB
                                     + ((lane & 8) ? 16 : 0));

    float acc[2][4][4];
    #pragma unroll
    for (int i = 0; i < 2; i++)
        #pragma unroll
        for (int j = 0; j < 4; j++)
            #pragma unroll
            for (int k = 0; k < 4; k++) acc[i][j][k] = 0.0f;

    // Prologue: raw A(0),A(1); B(0),B(1) committed; A(0) staged; B(0) landed.
    ldgA(0);
    ldgA(1);
    cpB(0);
    cpB(1);
    stsA(0);               // chains on raw bank0 (one-time stall)
    cp_wait<1>();          // B(0) done
    __syncthreads();       // publish stage0

    for (int kt = 0; kt < CHUNKS; kt++) {
        // Future loads first: everything issued here has >= 1 full iteration
        // (plus this iteration's MMA) in flight before anyone waits on it.
        if (kt + 2 < CHUNKS) {
            ldgA(kt + 2);          // raw regs, bank (kt)&1 (freed by stsA(kt) last iter)
            cpB(kt + 2);           // stage (kt+2)%4: disjoint from all live readers
        } else {
            cp_commit();           // keep one group per iteration
        }
        if (kt + 1 < CHUNKS) {
            stsA(kt + 1);          // raw loaded one full iteration ago: ready
        }
        cp_wait<2>();              // B(kt) complete (committed 2 iterations ago)
        __syncthreads();           // publish A(kt+1)/B(kt+1)-wait + free stage reads

        // MMA chunk kt from stage kt%4
        const uint32_t aaddr = stage(kt) + a_lm;
        const uint32_t baddr = stage(kt) + A_BYTES + b_lm;
        #pragma unroll
        for (int ks = 0; ks < 4; ks++) {
            uint32_t a[2][4];
            #pragma unroll
            for (int mt = 0; mt < 2; mt++)
                ldm4(a[mt][0], a[mt][1], a[mt][2], a[mt][3],
                     aaddr + (uint32_t)(mt * 16 * ROWB + ks * 32));
            uint32_t b[2][4];
            #pragma unroll
            for (int np = 0; np < 2; np++)
                ldm4(b[np][0], b[np][1], b[np][2], b[np][3],
                     baddr + (uint32_t)(np * 16 * ROWB + ks * 32));
            #pragma unroll
            for (int mt = 0; mt < 2; mt++)
                #pragma unroll
                for (int nt = 0; nt < 4; nt++)
                    mma16816(acc[mt][nt], a[mt], b[nt >> 1][(nt & 1) * 2],
                             b[nt >> 1][(nt & 1) * 2 + 1]);
        }
    }

    // Epilogue: scale + store
    const float fs = qsc[0] * ksc[0];
    float* outp = out + ((size_t)bh * S_ + (size_t)mblk * MT) * D_;
    #pragma unroll
    for (int mt = 0; mt < 2; mt++) {
        const int r0 = wm + mt * 16 + (lane >> 2);
        #pragma unroll
        for (int nt = 0; nt < 4; nt++) {
            const int col = wn + nt * 8 + (lane & 3) * 2;
            float2 v0 = make_float2(acc[mt][nt][0] * fs, acc[mt][nt][1] * fs);
            float2 v1 = make_float2(acc[mt][nt][2] * fs, acc[mt][nt][3] * fs);
            *reinterpret_cast<float2*>(outp + (size_t)r0 * D_ + col) = v0;
            *reinterpret_cast<float2*>(outp + (size_t)(r0 + 8) * D_ + col) = v1;
        }
    }
}

// ---------------------------------------------------------------------------
extern "C" void kernel_launch(void* const* d_in, const int* in_sizes, int n_in,
                              void* d_out, int out_size) {
    const float* score = (const float*)d_in[0];
    const float* value = (const float*)d_in[1];
    const float* qsc   = (const float*)d_in[2];
    const float* ksc   = (const float*)d_in[3];
    float* out = (float*)d_out;
    (void)in_sizes; (void)n_in; (void)out_size;

    dim3 g1(S_ / 32, D_ / 32, BH);
    dim3 b1(32, 8);
    quant_transpose_v<<<g1, b1>>>(value, ksc);

    cudaFuncSetAttribute(sqbmm_gemm, cudaFuncAttributeMaxDynamicSharedMemorySize, SMEM_TOTAL);
    sqbmm_gemm<<<BH * (S_ / MT), 256, SMEM_TOTAL>>>(score, qsc, ksc, out);
}

// round 15
// speedup vs baseline: 2.3419x; 2.3419x over previous
#include <cuda_runtime.h>
#include <cuda_bf16.h>
#include <cstdint>

#define DEVINL __device__ __forceinline__

// Shapes: score [2,16,2048,2048] f32, value [2,16,2048,128] f32 -> out [2,16,2048,128] f32
static constexpr int S_ = 2048;
static constexpr int D_ = 128;
static constexpr int BH = 32;
static constexpr int KB = 64;            // K per chunk
static constexpr int CHUNKS = S_ / KB;   // 32

// Padded smem tiles: rows of 64 bf16 + 8 pad = 72 elems = 144 bytes
static constexpr int ROWB = 144;
static constexpr int A_BYTES = 128 * ROWB;        // 18432
static constexpr int B_BYTES = 128 * ROWB;        // 18432
static constexpr int BUF_BYTES = A_BYTES + B_BYTES;
static constexpr int SMEM_TOTAL = 2 * BUF_BYTES;  // 73728

// Prequantized+transposed value: vt[bh][d][k] bf16, K contiguous (16 MB scratch)
__device__ __align__(16) __nv_bfloat16 g_vt[(size_t)BH * D_ * S_];

DEVINL uint32_t smem_u32(const void* p) {
    uint32_t a;
    asm("{ .reg .u64 t; cvta.to.shared.u64 t, %1; cvt.u32.u64 %0, t; }" : "=r"(a) : "l"(p));
    return a;
}

// Quantize: round-half-even(x/scale) clamped to [-129, 127] (faithful to reference)
DEVINL float quant1(float x, float inv) {
    return fminf(fmaxf(rintf(x * inv), -129.0f), 127.0f);
}
DEVINL uint32_t packq2(float a, float b, float inv) {
    __nv_bfloat162 h = __floats2bfloat162_rn(quant1(a, inv), quant1(b, inv));
    return *reinterpret_cast<uint32_t*>(&h);
}

DEVINL void cp_async16(uint32_t saddr, const void* gaddr) {
    asm volatile("cp.async.cg.shared.global [%0], [%1], 16;" :: "r"(saddr), "l"(gaddr));
}
DEVINL void cp_commit() { asm volatile("cp.async.commit_group;"); }
DEVINL void cp_wait0()  { asm volatile("cp.async.wait_group 0;" ::: "memory"); }

DEVINL void prefetch_l2(const void* gaddr) {
    asm volatile("prefetch.global.L2 [%0];" :: "l"(gaddr));
}

DEVINL void ldm4(uint32_t& r0, uint32_t& r1, uint32_t& r2, uint32_t& r3, uint32_t addr) {
    asm volatile("ldmatrix.sync.aligned.m8n8.x4.shared.b16 {%0,%1,%2,%3}, [%4];"
                 : "=r"(r0), "=r"(r1), "=r"(r2), "=r"(r3) : "r"(addr));
}

DEVINL void mma16816(float* c, const uint32_t* a, uint32_t b0, uint32_t b1) {
    asm volatile(
        "mma.sync.aligned.m16n8k16.row.col.f32.bf16.bf16.f32 "
        "{%0,%1,%2,%3}, {%4,%5,%6,%7}, {%8,%9}, {%0,%1,%2,%3};"
        : "+f"(c[0]), "+f"(c[1]), "+f"(c[2]), "+f"(c[3])
        : "r"(a[0]), "r"(a[1]), "r"(a[2]), "r"(a[3]), "r"(b0), "r"(b1));
}

// ---------------------------------------------------------------------------
// Kernel 1: quantize + transpose value -> g_vt[bh][d][k]
// ---------------------------------------------------------------------------
__global__ void quant_transpose_v(const float* __restrict__ value,
                                  const float* __restrict__ ksc) {
    __shared__ __nv_bfloat16 tile[32][34];
    const float inv = 1.0f / ksc[0];
    const int bh = blockIdx.z;
    const int kt = blockIdx.x;   // 64 tiles along K
    const int dt = blockIdx.y;   // 4 tiles along D
    const int tx = threadIdx.x;  // 32
    const int ty = threadIdx.y;  // 8

    const float* vp = value + ((size_t)bh * S_ + (size_t)kt * 32) * D_ + dt * 32;
    #pragma unroll
    for (int j = 0; j < 4; j++) {
        int k = ty + 8 * j;
        tile[k][tx] = __float2bfloat16(quant1(vp[(size_t)k * D_ + tx], inv));
    }
    __syncthreads();
    __nv_bfloat16* op = g_vt + ((size_t)bh * D_ + (size_t)dt * 32) * S_ + kt * 32;
    #pragma unroll
    for (int j = 0; j < 4; j++) {
        int d = ty + 8 * j;
        op[(size_t)d * S_ + tx] = tile[tx][d];
    }
}

// ---------------------------------------------------------------------------
// Kernel 2: fused quantize(score) + bf16 mma.sync GEMM (fp32 accum)
// CTA: 256 threads = 8 warps (2x4), tile M128 x N128, K chunk 64, double buffer.
// R4 skeleton + L2 prefetch of A two chunks ahead (fire-and-forget MLP).
// ---------------------------------------------------------------------------
__global__ void __launch_bounds__(256, 2)
sqbmm_gemm(const float* __restrict__ score,
           const float* __restrict__ qsc,
           const float* __restrict__ ksc,
           float* __restrict__ out) {
    extern __shared__ char smem[];
    const uint32_t sb = smem_u32(smem);
    const int tid  = threadIdx.x;
    const int lane = tid & 31;
    const int w    = tid >> 5;
    const int bx   = blockIdx.x;
    const int bh   = bx >> 4;
    const int mblk = bx & 15;

    const float inv_q = 1.0f / qsc[0];
    const float* arow = score + ((size_t)bh * S_ + (size_t)mblk * 128) * S_;
    const __nv_bfloat16* bbase = g_vt + (size_t)bh * D_ * S_;

    // warp tile: 64 (m) x 32 (n); warp grid 2x4
    const int wm = (w >> 2) * 64;
    const int wn = (w & 3) * 32;

    // ldmatrix per-lane base addresses (byte offsets within a buffer)
    const uint32_t a_lm = (uint32_t)((wm + (lane & 15)) * ROWB + (lane >> 4) * 16);
    const uint32_t b_lm = (uint32_t)((wn + (lane & 7) + ((lane & 16) ? 8 : 0)) * ROWB
                                     + ((lane & 8) ? 16 : 0));

    float acc[4][4][4];
    #pragma unroll
    for (int i = 0; i < 4; i++)
        #pragma unroll
        for (int j = 0; j < 4; j++)
            #pragma unroll
            for (int k = 0; k < 4; k++) acc[i][j][k] = 0.0f;

    uint32_t areg[16];

    auto load_a_regs = [&](int kk) {
        #pragma unroll
        for (int i = 0; i < 8; i++) {
            int idx = tid + i * 256;
            int row = idx >> 4;
            int c4  = idx & 15;
            float4 f = *reinterpret_cast<const float4*>(arow + (size_t)row * S_ + kk + c4 * 4);
            areg[2 * i]     = packq2(f.x, f.y, inv_q);
            areg[2 * i + 1] = packq2(f.z, f.w, inv_q);
        }
    };
    // Fire-and-forget: warm L2 with the A lines this thread will LDG later.
    auto prefetch_a = [&](int kk) {
        #pragma unroll
        for (int i = 0; i < 8; i++) {
            int idx = tid + i * 256;
            int row = idx >> 4;
            int c4  = idx & 15;
            prefetch_l2(arow + (size_t)row * S_ + kk + c4 * 4);
        }
    };
    auto sts_a_regs = [&](uint32_t abuf) {
        #pragma unroll
        for (int i = 0; i < 8; i++) {
            int idx = tid + i * 256;
            int row = idx >> 4;
            int c4  = idx & 15;
            uint32_t off = abuf + (uint32_t)(row * ROWB + c4 * 8);
            asm volatile("st.shared.v2.b32 [%0], {%1,%2};"
                         :: "r"(off), "r"(areg[2 * i]), "r"(areg[2 * i + 1]) : "memory");
        }
    };
    auto cp_b = [&](uint32_t bbuf, int kk) {
        #pragma unroll
        for (int i = 0; i < 4; i++) {
            int idx = tid + i * 256;
            int d = idx >> 3;
            int c = idx & 7;
            cp_async16(bbuf + (uint32_t)(d * ROWB + c * 16),
                       bbase + (size_t)d * S_ + kk + c * 8);
        }
        cp_commit();
    };

    // prologue: fill buffer 0 with chunk 0; prefetch chunk 1
    cp_b(sb + A_BYTES, 0);
    prefetch_a(KB);
    load_a_regs(0);
    sts_a_regs(sb);
    cp_wait0();
    __syncthreads();

    for (int kt = 0; kt < CHUNKS; kt++) {
        const int cur = kt & 1;
        const uint32_t bufc   = sb + (uint32_t)(cur * BUF_BYTES);
        const uint32_t abuf_n = sb + (uint32_t)((cur ^ 1) * BUF_BYTES);

        if (kt + 1 < CHUNKS) {
            cp_b(abuf_n + A_BYTES, (kt + 1) * KB);
            if (kt + 2 < CHUNKS) prefetch_a((kt + 2) * KB);  // DRAM->L2, 2 chunks lead
            load_a_regs((kt + 1) * KB);                      // mostly L2 hits now
        }

        // MMA over current buffer: 4 k-steps of 16
        const uint32_t aaddr = bufc + a_lm;
        const uint32_t baddr = bufc + A_BYTES + b_lm;
        #pragma unroll
        for (int ks = 0; ks < 4; ks++) {
            uint32_t a[4][4];
            #pragma unroll
            for (int mt = 0; mt < 4; mt++)
                ldm4(a[mt][0], a[mt][1], a[mt][2], a[mt][3],
                     aaddr + (uint32_t)(mt * 16 * ROWB + ks * 32));
            uint32_t b[2][4];
            #pragma unroll
            for (int np = 0; np < 2; np++)
                ldm4(b[np][0], b[np][1], b[np][2], b[np][3],
                     baddr + (uint32_t)(np * 16 * ROWB + ks * 32));
            #pragma unroll
            for (int mt = 0; mt < 4; mt++)
                #pragma unroll
                for (int nt = 0; nt < 4; nt++)
                    mma16816(acc[mt][nt], a[mt], b[nt >> 1][(nt & 1) * 2],
                             b[nt >> 1][(nt & 1) * 2 + 1]);
        }

        if (kt + 1 < CHUNKS) {
            sts_a_regs(abuf_n);
            cp_wait0();
        }
        __syncthreads();
    }

    // epilogue: scale + store
    const float fs = qsc[0] * ksc[0];
    float* outp = out + ((size_t)bh * S_ + (size_t)mblk * 128) * D_;
    #pragma unroll
    for (int mt = 0; mt < 4; mt++) {
        const int r0 = wm + mt * 16 + (lane >> 2);
        #pragma unroll
        for (int nt = 0; nt < 4; nt++) {
            const int col = wn + nt * 8 + (lane & 3) * 2;
            float2 v0 = make_float2(acc[mt][nt][0] * fs, acc[mt][nt][1] * fs);
            float2 v1 = make_float2(acc[mt][nt][2] * fs, acc[mt][nt][3] * fs);
            *reinterpret_cast<float2*>(outp + (size_t)r0 * D_ + col) = v0;
            *reinterpret_cast<float2*>(outp + (size_t)(r0 + 8) * D_ + col) = v1;
        }
    }
}

// ---------------------------------------------------------------------------
extern "C" void kernel_launch(void* const* d_in, const int* in_sizes, int n_in,
                              void* d_out, int out_size) {
    const float* score = (const float*)d_in[0];
    const float* value = (const float*)d_in[1];
    const float* qsc   = (const float*)d_in[2];
    const float* ksc   = (const float*)d_in[3];
    float* out = (float*)d_out;
    (void)in_sizes; (void)n_in; (void)out_size;

    dim3 g1(S_ / 32, D_ / 32, BH);
    dim3 b1(32, 8);
    quant_transpose_v<<<g1, b1>>>(value, ksc);

    cudaFuncSetAttribute(sqbmm_gemm, cudaFuncAttributeMaxDynamicSharedMemorySize, SMEM_TOTAL);
    sqbmm_gemm<<<BH * (S_ / 128), 256, SMEM_TOTAL>>>(score, qsc, ksc, out);
}

// round 16
// speedup vs baseline: 2.4033x; 1.0262x over previous
#include <cuda_runtime.h>
#include <cuda_bf16.h>
#include <cstdint>

#define DEVINL __device__ __forceinline__

// Shapes: score [2,16,2048,2048] f32, value [2,16,2048,128] f32 -> out [2,16,2048,128] f32
static constexpr int S_ = 2048;
static constexpr int D_ = 128;
static constexpr int BH = 32;
static constexpr int KB = 64;            // K per chunk
static constexpr int CHUNKS = S_ / KB;   // 32

// Padded smem tiles: rows of 64 bf16 + 8 pad = 72 elems = 144 bytes
static constexpr int ROWB = 144;
static constexpr int A_BYTES = 128 * ROWB;        // 18432
static constexpr int B_BYTES = 128 * ROWB;        // 18432
static constexpr int BUF_BYTES = A_BYTES + B_BYTES;
static constexpr int SMEM_TOTAL = 2 * BUF_BYTES;  // 73728

// Prequantized+transposed value: vt[bh][d][k] bf16, K contiguous (16 MB scratch)
__device__ __align__(16) __nv_bfloat16 g_vt[(size_t)BH * D_ * S_];

// 1.5 * 2^23: magic round-to-nearest-even constant, packed f32x2
static constexpr uint64_t MAGIC2    = 0x4B4000004B400000ull;
static constexpr uint64_t NEGMAGIC2 = 0xCB400000CB400000ull;

DEVINL uint32_t smem_u32(const void* p) {
    uint32_t a;
    asm("{ .reg .u64 t; cvta.to.shared.u64 t, %1; cvt.u32.u64 %0, t; }" : "=r"(a) : "l"(p));
    return a;
}

// Quantize: round-half-even(x/scale) clamped to [-129, 127] (faithful to reference)
DEVINL float quant1(float x, float inv) {
    return fminf(fmaxf(rintf(x * inv), -129.0f), 127.0f);
}

// Packed quantize of 2 fp32 (as raw b64) -> 1 bf16x2.
// fma.rn.f32x2 with the magic constant rounds both lanes to integer (RNE);
// values beyond +-2^22 are far outside [-129,127] and clamp correctly anyway.
DEVINL uint32_t packq2x2(uint64_t xy, uint64_t inv2) {
    uint64_t r;
    asm("fma.rn.f32x2 %0, %1, %2, %3;" : "=l"(r) : "l"(xy), "l"(inv2), "l"(MAGIC2));
    asm("add.rn.f32x2 %0, %0, %1;" : "+l"(r) : "l"(NEGMAGIC2));
    uint32_t lo32, hi32;
    asm("mov.b64 {%0, %1}, %2;" : "=r"(lo32), "=r"(hi32) : "l"(r));
    float lo = fminf(fmaxf(__uint_as_float(lo32), -129.0f), 127.0f);
    float hi = fminf(fmaxf(__uint_as_float(hi32), -129.0f), 127.0f);
    __nv_bfloat162 h = __floats2bfloat162_rn(lo, hi);
    return *reinterpret_cast<uint32_t*>(&h);
}

DEVINL void cp_async16(uint32_t saddr, const void* gaddr) {
    asm volatile("cp.async.cg.shared.global [%0], [%1], 16;" :: "r"(saddr), "l"(gaddr));
}
DEVINL void cp_commit() { asm volatile("cp.async.commit_group;"); }
DEVINL void cp_wait0()  { asm volatile("cp.async.wait_group 0;" ::: "memory"); }

DEVINL void ldm4(uint32_t& r0, uint32_t& r1, uint32_t& r2, uint32_t& r3, uint32_t addr) {
    asm volatile("ldmatrix.sync.aligned.m8n8.x4.shared.b16 {%0,%1,%2,%3}, [%4];"
                 : "=r"(r0), "=r"(r1), "=r"(r2), "=r"(r3) : "r"(addr));
}

DEVINL void mma16816(float* c, const uint32_t* a, uint32_t b0, uint32_t b1) {
    asm volatile(
        "mma.sync.aligned.m16n8k16.row.col.f32.bf16.bf16.f32 "
        "{%0,%1,%2,%3}, {%4,%5,%6,%7}, {%8,%9}, {%0,%1,%2,%3};"
        : "+f"(c[0]), "+f"(c[1]), "+f"(c[2]), "+f"(c[3])
        : "r"(a[0]), "r"(a[1]), "r"(a[2]), "r"(a[3]), "r"(b0), "r"(b1));
}

// ---------------------------------------------------------------------------
// Kernel 1: quantize + transpose value -> g_vt[bh][d][k]
// ---------------------------------------------------------------------------
__global__ void quant_transpose_v(const float* __restrict__ value,
                                  const float* __restrict__ ksc) {
    __shared__ __nv_bfloat16 tile[32][34];
    const float inv = 1.0f / ksc[0];
    const int bh = blockIdx.z;
    const int kt = blockIdx.x;   // 64 tiles along K
    const int dt = blockIdx.y;   // 4 tiles along D
    const int tx = threadIdx.x;  // 32
    const int ty = threadIdx.y;  // 8

    const float* vp = value + ((size_t)bh * S_ + (size_t)kt * 32) * D_ + dt * 32;
    #pragma unroll
    for (int j = 0; j < 4; j++) {
        int k = ty + 8 * j;
        tile[k][tx] = __float2bfloat16(quant1(vp[(size_t)k * D_ + tx], inv));
    }
    __syncthreads();
    __nv_bfloat16* op = g_vt + ((size_t)bh * D_ + (size_t)dt * 32) * S_ + kt * 32;
    #pragma unroll
    for (int j = 0; j < 4; j++) {
        int d = ty + 8 * j;
        op[(size_t)d * S_ + tx] = tile[tx][d];
    }
}

// ---------------------------------------------------------------------------
// Kernel 2: fused quantize(score) + bf16 mma.sync GEMM (fp32 accum)
// CTA: 256 threads = 8 warps (2x4), tile M128 x N128, K chunk 64, double buffer.
// R4 skeleton; quantize via packed f32x2 magic rounding.
// ---------------------------------------------------------------------------
__global__ void __launch_bounds__(256, 2)
sqbmm_gemm(const float* __restrict__ score,
           const float* __restrict__ qsc,
           const float* __restrict__ ksc,
           float* __restrict__ out) {
    extern __shared__ char smem[];
    const uint32_t sb = smem_u32(smem);
    const int tid  = threadIdx.x;
    const int lane = tid & 31;
    const int w    = tid >> 5;
    const int bx   = blockIdx.x;
    const int bh   = bx >> 4;
    const int mblk = bx & 15;

    const float inv_q = 1.0f / qsc[0];
    uint64_t inv2;
    asm("mov.b64 %0, {%1, %1};" : "=l"(inv2) : "f"(inv_q));

    const float* arow = score + ((size_t)bh * S_ + (size_t)mblk * 128) * S_;
    const __nv_bfloat16* bbase = g_vt + (size_t)bh * D_ * S_;

    // warp tile: 64 (m) x 32 (n); warp grid 2x4
    const int wm = (w >> 2) * 64;
    const int wn = (w & 3) * 32;

    // ldmatrix per-lane base addresses (byte offsets within a buffer)
    const uint32_t a_lm = (uint32_t)((wm + (lane & 15)) * ROWB + (lane >> 4) * 16);
    const uint32_t b_lm = (uint32_t)((wn + (lane & 7) + ((lane & 16) ? 8 : 0)) * ROWB
                                     + ((lane & 8) ? 16 : 0));

    float acc[4][4][4];
    #pragma unroll
    for (int i = 0; i < 4; i++)
        #pragma unroll
        for (int j = 0; j < 4; j++)
            #pragma unroll
            for (int k = 0; k < 4; k++) acc[i][j][k] = 0.0f;

    uint32_t areg[16];

    auto load_a_regs = [&](int kk) {
        #pragma unroll
        for (int i = 0; i < 8; i++) {
            int idx = tid + i * 256;
            int row = idx >> 4;
            int c4  = idx & 15;
            ulonglong2 u = *reinterpret_cast<const ulonglong2*>(
                arow + (size_t)row * S_ + kk + c4 * 4);
            areg[2 * i]     = packq2x2(u.x, inv2);
            areg[2 * i + 1] = packq2x2(u.y, inv2);
        }
    };
    auto sts_a_regs = [&](uint32_t abuf) {
        #pragma unroll
        for (int i = 0; i < 8; i++) {
            int idx = tid + i * 256;
            int row = idx >> 4;
            int c4  = idx & 15;
            uint32_t off = abuf + (uint32_t)(row * ROWB + c4 * 8);
            asm volatile("st.shared.v2.b32 [%0], {%1,%2};"
                         :: "r"(off), "r"(areg[2 * i]), "r"(areg[2 * i + 1]) : "memory");
        }
    };
    auto cp_b = [&](uint32_t bbuf, int kk) {
        #pragma unroll
        for (int i = 0; i < 4; i++) {
            int idx = tid + i * 256;
            int d = idx >> 3;
            int c = idx & 7;
            cp_async16(bbuf + (uint32_t)(d * ROWB + c * 16),
                       bbase + (size_t)d * S_ + kk + c * 8);
        }
        cp_commit();
    };

    // prologue: fill buffer 0 with chunk 0
    cp_b(sb + A_BYTES, 0);
    load_a_regs(0);
    sts_a_regs(sb);
    cp_wait0();
    __syncthreads();

    for (int kt = 0; kt < CHUNKS; kt++) {
        const int cur = kt & 1;
        const uint32_t bufc   = sb + (uint32_t)(cur * BUF_BYTES);
        const uint32_t abuf_n = sb + (uint32_t)((cur ^ 1) * BUF_BYTES);

        if (kt + 1 < CHUNKS) {
            cp_b(abuf_n + A_BYTES, (kt + 1) * KB);
            load_a_regs((kt + 1) * KB);
        }

        // MMA over current buffer: 4 k-steps of 16
        const uint32_t aaddr = bufc + a_lm;
        const uint32_t baddr = bufc + A_BYTES + b_lm;
        #pragma unroll
        for (int ks = 0; ks < 4; ks++) {
            uint32_t a[4][4];
            #pragma unroll
            for (int mt = 0; mt < 4; mt++)
                ldm4(a[mt][0], a[mt][1], a[mt][2], a[mt][3],
                     aaddr + (uint32_t)(mt * 16 * ROWB + ks * 32));
            uint32_t b[2][4];
            #pragma unroll
            for (int np = 0; np < 2; np++)
                ldm4(b[np][0], b[np][1], b[np][2], b[np][3],
                     baddr + (uint32_t)(np * 16 * ROWB + ks * 32));
            #pragma unroll
            for (int mt = 0; mt < 4; mt++)
                #pragma unroll
                for (int nt = 0; nt < 4; nt++)
                    mma16816(acc[mt][nt], a[mt], b[nt >> 1][(nt & 1) * 2],
                             b[nt >> 1][(nt & 1) * 2 + 1]);
        }

        if (kt + 1 < CHUNKS) {
            sts_a_regs(abuf_n);
            cp_wait0();
        }
        __syncthreads();
    }

    // epilogue: scale + store
    const float fs = qsc[0] * ksc[0];
    float* outp = out + ((size_t)bh * S_ + (size_t)mblk * 128) * D_;
    #pragma unroll
    for (int mt = 0; mt < 4; mt++) {
        const int r0 = wm + mt * 16 + (lane >> 2);
        #pragma unroll
        for (int nt = 0; nt < 4; nt++) {
            const int col = wn + nt * 8 + (lane & 3) * 2;
            float2 v0 = make_float2(acc[mt][nt][0] * fs, acc[mt][nt][1] * fs);
            float2 v1 = make_float2(acc[mt][nt][2] * fs, acc[mt][nt][3] * fs);
            *reinterpret_cast<float2*>(outp + (size_t)r0 * D_ + col) = v0;
            *reinterpret_cast<float2*>(outp + (size_t)(r0 + 8) * D_ + col) = v1;
        }
    }
}

// ---------------------------------------------------------------------------
extern "C" void kernel_launch(void* const* d_in, const int* in_sizes, int n_in,
                              void* d_out, int out_size) {
    const float* score = (const float*)d_in[0];
    const float* value = (const float*)d_in[1];
    const float* qsc   = (const float*)d_in[2];
    const float* ksc   = (const float*)d_in[3];
    float* out = (float*)d_out;
    (void)in_sizes; (void)n_in; (void)out_size;

    dim3 g1(S_ / 32, D_ / 32, BH);
    dim3 b1(32, 8);
    quant_transpose_v<<<g1, b1>>>(value, ksc);

    cudaFuncSetAttribute(sqbmm_gemm, cudaFuncAttributeMaxDynamicSharedMemorySize, SMEM_TOTAL);
    sqbmm_gemm<<<BH * (S_ / 128), 256, SMEM_TOTAL>>>(score, qsc, ksc, out);
}

// round 17
// speedup vs baseline: 2.4680x; 1.0269x over previous
#include <cuda_runtime.h>
#include <cuda_bf16.h>
#include <cstdint>

#define DEVINL __device__ __forceinline__

// Shapes: score [2,16,2048,2048] f32, value [2,16,2048,128] f32 -> out [2,16,2048,128] f32
static constexpr int S_ = 2048;
static constexpr int D_ = 128;
static constexpr int BH = 32;
static constexpr int KB = 64;            // K per chunk
static constexpr int CHUNKS = S_ / KB;   // 32

// Padded smem tiles: rows of 64 bf16 + 8 pad = 72 elems = 144 bytes
static constexpr int ROWB = 144;
static constexpr int A_BYTES = 128 * ROWB;        // 18432
static constexpr int B_BYTES = 128 * ROWB;        // 18432
static constexpr int BUF_BYTES = A_BYTES + B_BYTES;
static constexpr int SMEM_TOTAL = 2 * BUF_BYTES;  // 73728

// Prequantized+transposed value: vt[bh][d][k] bf16, K contiguous (16 MB scratch)
__device__ __align__(16) __nv_bfloat16 g_vt[(size_t)BH * D_ * S_];

// 1.5 * 2^23: magic round-to-nearest-even constant, packed f32x2
static constexpr uint64_t MAGIC2    = 0x4B4000004B400000ull;
static constexpr uint64_t NEGMAGIC2 = 0xCB400000CB400000ull;
// bf16x2 clamp bounds: (-129,-129) and (127,127); both exact in bf16.
static constexpr uint32_t BF2_LO = 0xC301C301u;   // -129.0 x2
static constexpr uint32_t BF2_HI = 0x42FE42FEu;   // 127.0 x2

DEVINL uint32_t smem_u32(const void* p) {
    uint32_t a;
    asm("{ .reg .u64 t; cvta.to.shared.u64 t, %1; cvt.u32.u64 %0, t; }" : "=r"(a) : "l"(p));
    return a;
}

// Quantize: round-half-even(x/scale) clamped to [-129, 127] (faithful to reference)
DEVINL float quant1(float x, float inv) {
    return fminf(fmaxf(rintf(x * inv), -129.0f), 127.0f);
}

// Packed quantize of 2 fp32 (as raw b64) -> 1 bf16x2.
// fma.rn.f32x2 + magic rounds both lanes to integer (RNE). Integers are exact
// in bf16 up to 256 and anything larger clamps, so the clamp runs in bf16x2
// domain (hmax2/hmin2) after the convert. -129 and 127 are bf16-exact.
DEVINL uint32_t packq2x2(uint64_t xy, uint64_t inv2) {
    uint64_t r;
    asm("fma.rn.f32x2 %0, %1, %2, %3;" : "=l"(r) : "l"(xy), "l"(inv2), "l"(MAGIC2));
    asm("add.rn.f32x2 %0, %0, %1;" : "+l"(r) : "l"(NEGMAGIC2));
    uint32_t lo32, hi32;
    asm("mov.b64 {%0, %1}, %2;" : "=r"(lo32), "=r"(hi32) : "l"(r));
    uint32_t p;
    asm("cvt.rn.bf16x2.f32 %0, %1, %2;" : "=r"(p) : "r"(hi32), "r"(lo32));
    asm("max.bf16x2 %0, %0, %1;" : "+r"(p) : "r"(BF2_LO));
    asm("min.bf16x2 %0, %0, %1;" : "+r"(p) : "r"(BF2_HI));
    return p;
}

DEVINL void cp_async16(uint32_t saddr, const void* gaddr) {
    asm volatile("cp.async.cg.shared.global [%0], [%1], 16;" :: "r"(saddr), "l"(gaddr));
}
DEVINL void cp_commit() { asm volatile("cp.async.commit_group;"); }
DEVINL void cp_wait0()  { asm volatile("cp.async.wait_group 0;" ::: "memory"); }

DEVINL void ldm4(uint32_t& r0, uint32_t& r1, uint32_t& r2, uint32_t& r3, uint32_t addr) {
    asm volatile("ldmatrix.sync.aligned.m8n8.x4.shared.b16 {%0,%1,%2,%3}, [%4];"
                 : "=r"(r0), "=r"(r1), "=r"(r2), "=r"(r3) : "r"(addr));
}

DEVINL void mma16816(float* c, const uint32_t* a, uint32_t b0, uint32_t b1) {
    asm volatile(
        "mma.sync.aligned.m16n8k16.row.col.f32.bf16.bf16.f32 "
        "{%0,%1,%2,%3}, {%4,%5,%6,%7}, {%8,%9}, {%0,%1,%2,%3};"
        : "+f"(c[0]), "+f"(c[1]), "+f"(c[2]), "+f"(c[3])
        : "r"(a[0]), "r"(a[1]), "r"(a[2]), "r"(a[3]), "r"(b0), "r"(b1));
}

// ---------------------------------------------------------------------------
// Kernel 1: quantize + transpose value -> g_vt[bh][d][k]
// ---------------------------------------------------------------------------
__global__ void quant_transpose_v(const float* __restrict__ value,
                                  const float* __restrict__ ksc) {
    __shared__ __nv_bfloat16 tile[32][34];
    const float inv = 1.0f / ksc[0];
    const int bh = blockIdx.z;
    const int kt = blockIdx.x;   // 64 tiles along K
    const int dt = blockIdx.y;   // 4 tiles along D
    const int tx = threadIdx.x;  // 32
    const int ty = threadIdx.y;  // 8

    const float* vp = value + ((size_t)bh * S_ + (size_t)kt * 32) * D_ + dt * 32;
    #pragma unroll
    for (int j = 0; j < 4; j++) {
        int k = ty + 8 * j;
        tile[k][tx] = __float2bfloat16(quant1(vp[(size_t)k * D_ + tx], inv));
    }
    __syncthreads();
    __nv_bfloat16* op = g_vt + ((size_t)bh * D_ + (size_t)dt * 32) * S_ + kt * 32;
    #pragma unroll
    for (int j = 0; j < 4; j++) {
        int d = ty + 8 * j;
        op[(size_t)d * S_ + tx] = tile[tx][d];
    }
}

// ---------------------------------------------------------------------------
// Kernel 2: fused quantize(score) + bf16 mma.sync GEMM (fp32 accum)
// CTA: 256 threads = 8 warps (2x4), tile M128 x N128, K chunk 64, double buffer.
// R4/R16 skeleton; quantize via packed f32x2 magic round + bf16x2 clamp.
// ---------------------------------------------------------------------------
__global__ void __launch_bounds__(256, 2)
sqbmm_gemm(const float* __restrict__ score,
           const float* __restrict__ qsc,
           const float* __restrict__ ksc,
           float* __restrict__ out) {
    extern __shared__ char smem[];
    const uint32_t sb = smem_u32(smem);
    const int tid  = threadIdx.x;
    const int lane = tid & 31;
    const int w    = tid >> 5;
    const int bx   = blockIdx.x;
    const int bh   = bx >> 4;
    const int mblk = bx & 15;

    const float inv_q = 1.0f / qsc[0];
    uint64_t inv2;
    asm("mov.b64 %0, {%1, %1};" : "=l"(inv2) : "f"(inv_q));

    const float* arow = score + ((size_t)bh * S_ + (size_t)mblk * 128) * S_;
    const __nv_bfloat16* bbase = g_vt + (size_t)bh * D_ * S_;

    // warp tile: 64 (m) x 32 (n); warp grid 2x4
    const int wm = (w >> 2) * 64;
    const int wn = (w & 3) * 32;

    // ldmatrix per-lane base addresses (byte offsets within a buffer)
    const uint32_t a_lm = (uint32_t)((wm + (lane & 15)) * ROWB + (lane >> 4) * 16);
    const uint32_t b_lm = (uint32_t)((wn + (lane & 7) + ((lane & 16) ? 8 : 0)) * ROWB
                                     + ((lane & 8) ? 16 : 0));

    float acc[4][4][4];
    #pragma unroll
    for (int i = 0; i < 4; i++)
        #pragma unroll
        for (int j = 0; j < 4; j++)
            #pragma unroll
            for (int k = 0; k < 4; k++) acc[i][j][k] = 0.0f;

    uint32_t areg[16];

    auto load_a_regs = [&](int kk) {
        #pragma unroll
        for (int i = 0; i < 8; i++) {
            int idx = tid + i * 256;
            int row = idx >> 4;
            int c4  = idx & 15;
            ulonglong2 u = *reinterpret_cast<const ulonglong2*>(
                arow + (size_t)row * S_ + kk + c4 * 4);
            areg[2 * i]     = packq2x2(u.x, inv2);
            areg[2 * i + 1] = packq2x2(u.y, inv2);
        }
    };
    auto sts_a_regs = [&](uint32_t abuf) {
        #pragma unroll
        for (int i = 0; i < 8; i++) {
            int idx = tid + i * 256;
            int row = idx >> 4;
            int c4  = idx & 15;
            uint32_t off = abuf + (uint32_t)(row * ROWB + c4 * 8);
            asm volatile("st.shared.v2.b32 [%0], {%1,%2};"
                         :: "r"(off), "r"(areg[2 * i]), "r"(areg[2 * i + 1]) : "memory");
        }
    };
    auto cp_b = [&](uint32_t bbuf, int kk) {
        #pragma unroll
        for (int i = 0; i < 4; i++) {
            int idx = tid + i * 256;
            int d = idx >> 3;
            int c = idx & 7;
            cp_async16(bbuf + (uint32_t)(d * ROWB + c * 16),
                       bbase + (size_t)d * S_ + kk + c * 8);
        }
        cp_commit();
    };

    // prologue: fill buffer 0 with chunk 0
    cp_b(sb + A_BYTES, 0);
    load_a_regs(0);
    sts_a_regs(sb);
    cp_wait0();
    __syncthreads();

    for (int kt = 0; kt < CHUNKS; kt++) {
        const int cur = kt & 1;
        const uint32_t bufc   = sb + (uint32_t)(cur * BUF_BYTES);
        const uint32_t abuf_n = sb + (uint32_t)((cur ^ 1) * BUF_BYTES);

        if (kt + 1 < CHUNKS) {
            cp_b(abuf_n + A_BYTES, (kt + 1) * KB);
            load_a_regs((kt + 1) * KB);
        }

        // MMA over current buffer: 4 k-steps of 16
        const uint32_t aaddr = bufc + a_lm;
        const uint32_t baddr = bufc + A_BYTES + b_lm;
        #pragma unroll
        for (int ks = 0; ks < 4; ks++) {
            uint32_t a[4][4];
            #pragma unroll
            for (int mt = 0; mt < 4; mt++)
                ldm4(a[mt][0], a[mt][1], a[mt][2], a[mt][3],
                     aaddr + (uint32_t)(mt * 16 * ROWB + ks * 32));
            uint32_t b[2][4];
            #pragma unroll
            for (int np = 0; np < 2; np++)
                ldm4(b[np][0], b[np][1], b[np][2], b[np][3],
                     baddr + (uint32_t)(np * 16 * ROWB + ks * 32));
            #pragma unroll
            for (int mt = 0; mt < 4; mt++)
                #pragma unroll
                for (int nt = 0; nt < 4; nt++)
                    mma16816(acc[mt][nt], a[mt], b[nt >> 1][(nt & 1) * 2],
                             b[nt >> 1][(nt & 1) * 2 + 1]);
        }

        if (kt + 1 < CHUNKS) {
            sts_a_regs(abuf_n);
            cp_wait0();
        }
        __syncthreads();
    }

    // epilogue: scale + store
    const float fs = qsc[0] * ksc[0];
    float* outp = out + ((size_t)bh * S_ + (size_t)mblk * 128) * D_;
    #pragma unroll
    for (int mt = 0; mt < 4; mt++) {
        const int r0 = wm + mt * 16 + (lane >> 2);
        #pragma unroll
        for (int nt = 0; nt < 4; nt++) {
            const int col = wn + nt * 8 + (lane & 3) * 2;
            float2 v0 = make_float2(acc[mt][nt][0] * fs, acc[mt][nt][1] * fs);
            float2 v1 = make_float2(acc[mt][nt][2] * fs, acc[mt][nt][3] * fs);
            *reinterpret_cast<float2*>(outp + (size_t)r0 * D_ + col) = v0;
            *reinterpret_cast<float2*>(outp + (size_t)(r0 + 8) * D_ + col) = v1;
        }
    }
}

// ---------------------------------------------------------------------------
extern "C" void kernel_launch(void* const* d_in, const int* in_sizes, int n_in,
                              void* d_out, int out_size) {
    const float* score = (const float*)d_in[0];
    const float* value = (const float*)d_in[1];
    const float* qsc   = (const float*)d_in[2];
    const float* ksc   = (const float*)d_in[3];
    float* out = (float*)d_out;
    (void)in_sizes; (void)n_in; (void)out_size;

    dim3 g1(S_ / 32, D_ / 32, BH);
    dim3 b1(32, 8);
    quant_transpose_v<<<g1, b1>>>(value, ksc);

    cudaFuncSetAttribute(sqbmm_gemm, cudaFuncAttributeMaxDynamicSharedMemorySize, SMEM_TOTAL);
    sqbmm_gemm<<<BH * (S_ / 128), 256, SMEM_TOTAL>>>(score, qsc, ksc, out);
}